// round 2
// baseline (speedup 1.0000x reference)
#include <cuda_runtime.h>
#include <cuda_bf16.h>
#include <cstdint>

#define BATCH 16
#define HW 409600
#define HW4 102400
#define PB 100          // blocks per batch in big passes
#define CHUNK4 1024     // float4 elems per block
#define NT 256
#define NKC 5
#define EPSL 1e-6

// ---------------- scratch (device globals; no runtime allocation) ----------
__device__ unsigned int g_hist1[BATCH][65536];   // 4 MB
__device__ unsigned int g_hist2[BATCH][65536];   // 4 MB
__device__ unsigned int g_negbits[BATCH * HW];   // 26 MB: p-bits of negatives, 0 otherwise
__device__ double g_sp[BATCH], g_sp2[BATCH], g_sp2_above[BATCH], g_losstext[BATCH];
__device__ unsigned int g_npos[BATCH], g_nneg[BATCH], g_B1[BATCH], g_cntA[BATCH], g_k[BATCH];
__device__ double g_ki[BATCH * NKC], g_kii[BATCH * NKC], g_ktt[BATCH * NKC];

// ---------------- helpers ----------------
__device__ __forceinline__ float sigmoidf_fast(float x) {
    return 1.0f / (1.0f + __expf(-x));
}

// block reduce (result valid in thread 0); smem must hold >= 8 floats
__device__ __forceinline__ float blockReduceF(float v, float* s) {
    #pragma unroll
    for (int o = 16; o; o >>= 1) v += __shfl_down_sync(0xFFFFFFFFu, v, o);
    int lane = threadIdx.x & 31, w = threadIdx.x >> 5;
    if (lane == 0) s[w] = v;
    __syncthreads();
    v = (threadIdx.x < (blockDim.x >> 5)) ? s[threadIdx.x] : 0.0f;
    if (w == 0) {
        #pragma unroll
        for (int o = 4; o; o >>= 1) v += __shfl_down_sync(0xFFFFFFFFu, v, o);
    }
    __syncthreads();   // smem reusable after return
    return v;
}

// ---------------- kernels ----------------
__global__ void zero_kernel() {
    unsigned idx = blockIdx.x * blockDim.x + threadIdx.x;
    unsigned stride = gridDim.x * blockDim.x;
    const unsigned n = BATCH * 65536u;
    unsigned* h1 = &g_hist1[0][0];
    unsigned* h2 = &g_hist2[0][0];
    for (unsigned i = idx; i < n; i += stride) { h1[i] = 0u; h2[i] = 0u; }
    if (idx < BATCH) {
        g_sp[idx] = 0.0; g_sp2[idx] = 0.0; g_sp2_above[idx] = 0.0; g_losstext[idx] = 0.0;
        g_npos[idx] = 0u; g_nneg[idx] = 0u; g_B1[idx] = 0u; g_cntA[idx] = 0u; g_k[idx] = 0u;
    }
    if (idx < BATCH * NKC) { g_ki[idx] = 0.0; g_kii[idx] = 0.0; g_ktt[idx] = 0.0; }
}

__global__ void __launch_bounds__(NT) pass1_kernel(
    const float4* __restrict__ pred, const float4* __restrict__ gtt,
    const float4* __restrict__ gtk,  const float4* __restrict__ msk)
{
    __shared__ float sred[8];
    int b = blockIdx.x / PB;
    int base4 = (blockIdx.x % PB) * CHUNK4;

    const float4* m4 = msk + (size_t)b * HW4;
    const float4* g4 = gtt + (size_t)b * HW4;
    const float4* p4 = pred + (size_t)b * 6 * HW4;   // channel 0 = pred_text
    uint4* nb4 = reinterpret_cast<uint4*>(g_negbits) + (size_t)b * HW4;

    float4 mreg[4];
    float sp = 0.f, sp2 = 0.f, np = 0.f, nn = 0.f;

    #pragma unroll
    for (int i = 0; i < 4; i++) {
        int idx = base4 + threadIdx.x + i * NT;
        float4 mv = m4[idx]; mreg[i] = mv;
        float4 gv = g4[idx];
        float4 pv = p4[idx];
        uint4 ob;
        #define PROC(COMP)                                                        \
        {                                                                         \
            bool m = mv.COMP > 0.5f; bool g = gv.COMP > 0.5f;                     \
            float p = sigmoidf_fast(pv.COMP);                                     \
            unsigned bits = __float_as_uint(p);                                   \
            unsigned o = 0u;                                                      \
            if (m) {                                                              \
                if (g) { np += 1.f; sp += p; sp2 += p * p; }                      \
                else   { nn += 1.f; o = bits;                                     \
                         atomicAdd(&g_hist1[b][bits >> 16], 1u); }                \
            }                                                                     \
            ob.COMP = o;                                                          \
        }
        PROC(x) PROC(y) PROC(z) PROC(w)
        #undef PROC
        nb4[idx] = ob;
    }

    float t;
    t = blockReduceF(sp,  sred); if (threadIdx.x == 0) atomicAdd(&g_sp[b],  (double)t);
    t = blockReduceF(sp2, sred); if (threadIdx.x == 0) atomicAdd(&g_sp2[b], (double)t);
    t = blockReduceF(np,  sred); if (threadIdx.x == 0) atomicAdd(&g_npos[b], (unsigned)(t + 0.5f));
    t = blockReduceF(nn,  sred); if (threadIdx.x == 0) atomicAdd(&g_nneg[b], (unsigned)(t + 0.5f));

    // kernel dice channels
    #pragma unroll 1
    for (int c = 0; c < NKC; c++) {
        const float4* pk = pred + ((size_t)b * 6 + 1 + c) * HW4;
        const float4* gk = gtk  + ((size_t)b * NKC + c) * HW4;
        float inter = 0.f, sii = 0.f, stt = 0.f;
        #pragma unroll
        for (int i = 0; i < 4; i++) {
            int idx = base4 + threadIdx.x + i * NT;
            float4 pv = pk[idx]; float4 gv = gk[idx]; float4 mv = mreg[i];
            #define PROCK(COMP)                                                   \
            {                                                                     \
                if (mv.COMP > 0.5f) {                                             \
                    float s = sigmoidf_fast(pv.COMP);                             \
                    sii += s * s;                                                 \
                    if (gv.COMP > 0.5f) { inter += s; stt += 1.f; }               \
                }                                                                 \
            }
            PROCK(x) PROCK(y) PROCK(z) PROCK(w)
            #undef PROCK
        }
        int id = b * NKC + c;
        float r;
        r = blockReduceF(inter, sred); if (threadIdx.x == 0) atomicAdd(&g_ki[id],  (double)r);
        r = blockReduceF(sii,   sred); if (threadIdx.x == 0) atomicAdd(&g_kii[id], (double)r);
        r = blockReduceF(stt,   sred); if (threadIdx.x == 0) atomicAdd(&g_ktt[id], (double)r);
    }
}

// find high-16-bit bucket containing k-th largest negative score
__global__ void __launch_bounds__(1024) pass2_kernel() {
    int b = blockIdx.x;
    int t = threadIdx.x;
    __shared__ unsigned csum[1024];
    __shared__ unsigned suf[1024];
    __shared__ int sB1;
    __shared__ unsigned sCnt;

    unsigned npos = g_npos[b];
    unsigned nneg = g_nneg[b];
    unsigned k = 3u * npos; if (k > nneg) k = nneg;

    unsigned s = 0;
    #pragma unroll 8
    for (int j = 0; j < 64; j++) s += g_hist1[b][t * 64 + j];
    csum[t] = s;
    __syncthreads();
    if (t == 0) {
        unsigned acc = 0;
        for (int i = 1023; i >= 0; i--) { suf[i] = acc; acc += csum[i]; }
        sB1 = 0x7FFFFFFF;   // sentinel (k==0 case): never matched in pass3
        sCnt = 0u;
    }
    __syncthreads();
    if (k > 0) {
        unsigned before = suf[t];
        if (before < k && before + csum[t] >= k) {
            unsigned cum = before;
            for (int j = 63; j >= 0; j--) {
                unsigned c = g_hist1[b][t * 64 + j];
                if (cum + c >= k) { sB1 = t * 64 + j; sCnt = cum; break; }
                cum += c;
            }
        }
    }
    __syncthreads();
    if (t == 0) { g_k[b] = k; g_B1[b] = (unsigned)sB1; g_cntA[b] = sCnt; }
}

__global__ void __launch_bounds__(NT) pass3_kernel() {
    __shared__ float sred[8];
    int b = blockIdx.x / PB;
    int base4 = (blockIdx.x % PB) * CHUNK4;
    unsigned B1 = g_B1[b];
    const uint4* nb4 = reinterpret_cast<const uint4*>(g_negbits) + (size_t)b * HW4;

    float sp2a = 0.f;
    #pragma unroll
    for (int i = 0; i < 4; i++) {
        uint4 v = nb4[base4 + threadIdx.x + i * NT];
        #define PROC3(COMP)                                                       \
        {                                                                         \
            unsigned bits = v.COMP;                                               \
            if (bits) {                                                           \
                unsigned h = bits >> 16;                                          \
                if (h > B1) { float p = __uint_as_float(bits); sp2a += p * p; }   \
                else if (h == B1) atomicAdd(&g_hist2[b][bits & 0xFFFFu], 1u);     \
            }                                                                     \
        }
        PROC3(x) PROC3(y) PROC3(z) PROC3(w)
        #undef PROC3
    }
    float t = blockReduceF(sp2a, sred);
    if (threadIdx.x == 0) atomicAdd(&g_sp2_above[b], (double)t);
}

// resolve low 16 bits of threshold, exact hard-negative p^2 sum, per-batch text dice
__global__ void __launch_bounds__(1024) pass4_kernel() {
    int b = blockIdx.x;
    int t = threadIdx.x;
    __shared__ unsigned csum[1024];
    __shared__ unsigned suf[1024];
    __shared__ int sJ;
    __shared__ unsigned sCnt;
    __shared__ double dred[1024];

    unsigned k = g_k[b];
    unsigned cA = g_cntA[b];
    long long r = (long long)k - (long long)cA;
    unsigned B1 = g_B1[b];
    __shared__ double sHard;
    if (t == 0) sHard = g_sp2_above[b];

    if (r > 0) {
        unsigned s = 0;
        #pragma unroll 8
        for (int j = 0; j < 64; j++) s += g_hist2[b][t * 64 + j];
        csum[t] = s;
        __syncthreads();
        if (t == 0) {
            unsigned acc = 0;
            for (int i = 1023; i >= 0; i--) { suf[i] = acc; acc += csum[i]; }
            sJ = -1; sCnt = 0u;
        }
        __syncthreads();
        unsigned before = suf[t];
        if ((long long)before < r && (long long)(before + csum[t]) >= r) {
            unsigned cum = before;
            for (int j = 63; j >= 0; j--) {
                unsigned c = g_hist2[b][t * 64 + j];
                if ((long long)(cum + c) >= r) { sJ = t * 64 + j; sCnt = cum; break; }
                cum += c;
            }
        }
        __syncthreads();
        int jt = sJ;
        unsigned cAJ = sCnt;
        double ws = 0.0;
        for (int j = 0; j < 64; j++) {
            int gj = t * 64 + j;
            if (gj > jt) {
                unsigned c = g_hist2[b][gj];
                if (c) {
                    float v = __uint_as_float((B1 << 16) | (unsigned)gj);
                    ws += (double)c * (double)v * (double)v;
                }
            }
        }
        dred[t] = ws;
        __syncthreads();
        for (int o = 512; o; o >>= 1) {
            if (t < o) dred[t] += dred[t + o];
            __syncthreads();
        }
        if (t == 0) {
            float vt = __uint_as_float((B1 << 16) | (unsigned)jt);
            sHard += dred[0] + (double)(r - (long long)cAJ) * (double)vt * (double)vt;
        }
        __syncthreads();
    }
    if (t == 0) {
        double np = (double)g_npos[b];
        g_losstext[b] = 1.0 - 2.0 * g_sp[b] / (g_sp2[b] + sHard + np + EPSL);
    }
}

__global__ void final_kernel(float* out) {
    if (threadIdx.x == 0) {
        double lk = 0.0;
        for (int i = 0; i < BATCH * NKC; i++)
            lk += 1.0 - 2.0 * g_ki[i] / (g_kii[i] + g_ktt[i] + EPSL);
        lk /= (double)(BATCH * NKC);
        double lt = 0.0;
        for (int bb = 0; bb < BATCH; bb++) lt += g_losstext[bb];
        lt /= (double)BATCH;
        out[0] = (float)(lk + 0.5 * lt);
        out[1] = (float)lt;
        out[2] = (float)lk;
    }
}

// ---------------- launch ----------------
extern "C" void kernel_launch(void* const* d_in, const int* in_sizes, int n_in,
                              void* d_out, int out_size) {
    const float4* pred = (const float4*)d_in[0];
    const float4* gtt  = (const float4*)d_in[1];
    const float4* gtk  = (const float4*)d_in[2];
    const float4* msk  = (const float4*)d_in[3];
    float* out = (float*)d_out;

    zero_kernel<<<1024, 1024>>>();
    pass1_kernel<<<BATCH * PB, NT>>>(pred, gtt, gtk, msk);
    pass2_kernel<<<BATCH, 1024>>>();
    pass3_kernel<<<BATCH * PB, NT>>>();
    pass4_kernel<<<BATCH, 1024>>>();
    final_kernel<<<1, 32>>>(out);
}

// round 3
// speedup vs baseline: 1.0034x; 1.0034x over previous
#include <cuda_runtime.h>
#include <cuda_bf16.h>
#include <cstdint>

#define BATCH 16
#define HW 409600
#define HW4 102400
#define PB 100          // blocks per batch in big passes
#define CHUNK4 1024     // float4 elems per block
#define NT 256
#define NKC 5
#define EPSL 1e-6

// ---------------- scratch (device globals; no runtime allocation) ----------
__device__ unsigned int g_hist1[BATCH][65536];   // 4 MB
__device__ unsigned int g_hist2[BATCH][65536];   // 4 MB
__device__ unsigned int g_negbits[BATCH * HW];   // 26 MB: p-bits of negatives, 0 otherwise
__device__ double g_sp[BATCH], g_sp2[BATCH], g_sp2_above[BATCH], g_losstext[BATCH];
__device__ unsigned int g_npos[BATCH], g_nneg[BATCH], g_B1[BATCH], g_cntA[BATCH], g_k[BATCH];
__device__ double g_ki[BATCH * NKC], g_kii[BATCH * NKC], g_ktt[BATCH * NKC];

// ---------------- helpers ----------------
__device__ __forceinline__ float sigmoidf_fast(float x) {
    return 1.0f / (1.0f + __expf(-x));
}

// block reduce (result valid in thread 0); smem must hold >= 8 floats
__device__ __forceinline__ float blockReduceF(float v, float* s) {
    #pragma unroll
    for (int o = 16; o; o >>= 1) v += __shfl_down_sync(0xFFFFFFFFu, v, o);
    int lane = threadIdx.x & 31, w = threadIdx.x >> 5;
    if (lane == 0) s[w] = v;
    __syncthreads();
    v = (threadIdx.x < (blockDim.x >> 5)) ? s[threadIdx.x] : 0.0f;
    if (w == 0) {
        #pragma unroll
        for (int o = 4; o; o >>= 1) v += __shfl_down_sync(0xFFFFFFFFu, v, o);
    }
    __syncthreads();   // smem reusable after return
    return v;
}

// ---------------- kernels ----------------
__global__ void zero_kernel() {
    unsigned idx = blockIdx.x * blockDim.x + threadIdx.x;
    unsigned stride = gridDim.x * blockDim.x;
    const unsigned n = BATCH * 65536u;
    unsigned* h1 = &g_hist1[0][0];
    unsigned* h2 = &g_hist2[0][0];
    for (unsigned i = idx; i < n; i += stride) { h1[i] = 0u; h2[i] = 0u; }
    if (idx < BATCH) {
        g_sp[idx] = 0.0; g_sp2[idx] = 0.0; g_sp2_above[idx] = 0.0; g_losstext[idx] = 0.0;
        g_npos[idx] = 0u; g_nneg[idx] = 0u; g_B1[idx] = 0u; g_cntA[idx] = 0u; g_k[idx] = 0u;
    }
    if (idx < BATCH * NKC) { g_ki[idx] = 0.0; g_kii[idx] = 0.0; g_ktt[idx] = 0.0; }
}

__global__ void __launch_bounds__(NT) pass1_kernel(
    const float4* __restrict__ pred, const float4* __restrict__ gtt,
    const float4* __restrict__ gtk,  const float4* __restrict__ msk)
{
    __shared__ float sred[8];
    int b = blockIdx.x / PB;
    int base4 = (blockIdx.x % PB) * CHUNK4;

    const float4* m4 = msk + (size_t)b * HW4;
    const float4* g4 = gtt + (size_t)b * HW4;
    const float4* p4 = pred + (size_t)b * 6 * HW4;   // channel 0 = pred_text
    uint4* nb4 = reinterpret_cast<uint4*>(g_negbits) + (size_t)b * HW4;

    float4 mreg[4];
    float sp = 0.f, sp2 = 0.f, np = 0.f, nn = 0.f;

    #pragma unroll
    for (int i = 0; i < 4; i++) {
        int idx = base4 + threadIdx.x + i * NT;
        float4 mv = m4[idx]; mreg[i] = mv;
        float4 gv = g4[idx];
        float4 pv = p4[idx];
        uint4 ob;
        #define PROC(COMP)                                                        \
        {                                                                         \
            bool m = mv.COMP > 0.5f; bool g = gv.COMP > 0.5f;                     \
            float p = sigmoidf_fast(pv.COMP);                                     \
            unsigned bits = __float_as_uint(p);                                   \
            unsigned o = 0u;                                                      \
            if (m) {                                                              \
                if (g) { np += 1.f; sp += p; sp2 += p * p; }                      \
                else   { nn += 1.f; o = bits;                                     \
                         atomicAdd(&g_hist1[b][bits >> 16], 1u); }                \
            }                                                                     \
            ob.COMP = o;                                                          \
        }
        PROC(x) PROC(y) PROC(z) PROC(w)
        #undef PROC
        nb4[idx] = ob;
    }

    float t;
    t = blockReduceF(sp,  sred); if (threadIdx.x == 0) atomicAdd(&g_sp[b],  (double)t);
    t = blockReduceF(sp2, sred); if (threadIdx.x == 0) atomicAdd(&g_sp2[b], (double)t);
    t = blockReduceF(np,  sred); if (threadIdx.x == 0) atomicAdd(&g_npos[b], (unsigned)(t + 0.5f));
    t = blockReduceF(nn,  sred); if (threadIdx.x == 0) atomicAdd(&g_nneg[b], (unsigned)(t + 0.5f));

    // kernel dice channels
    #pragma unroll 1
    for (int c = 0; c < NKC; c++) {
        const float4* pk = pred + ((size_t)b * 6 + 1 + c) * HW4;
        const float4* gk = gtk  + ((size_t)b * NKC + c) * HW4;
        float inter = 0.f, sii = 0.f, stt = 0.f;
        #pragma unroll
        for (int i = 0; i < 4; i++) {
            int idx = base4 + threadIdx.x + i * NT;
            float4 pv = pk[idx]; float4 gv = gk[idx]; float4 mv = mreg[i];
            #define PROCK(COMP)                                                   \
            {                                                                     \
                if (mv.COMP > 0.5f) {                                             \
                    float s = sigmoidf_fast(pv.COMP);                             \
                    sii += s * s;                                                 \
                    if (gv.COMP > 0.5f) { inter += s; stt += 1.f; }               \
                }                                                                 \
            }
            PROCK(x) PROCK(y) PROCK(z) PROCK(w)
            #undef PROCK
        }
        int id = b * NKC + c;
        float r;
        r = blockReduceF(inter, sred); if (threadIdx.x == 0) atomicAdd(&g_ki[id],  (double)r);
        r = blockReduceF(sii,   sred); if (threadIdx.x == 0) atomicAdd(&g_kii[id], (double)r);
        r = blockReduceF(stt,   sred); if (threadIdx.x == 0) atomicAdd(&g_ktt[id], (double)r);
    }
}

// find high-16-bit bucket containing k-th largest negative score
__global__ void __launch_bounds__(1024) pass2_kernel() {
    int b = blockIdx.x;
    int t = threadIdx.x;
    __shared__ unsigned csum[1024];
    __shared__ unsigned suf[1024];
    __shared__ int sB1;
    __shared__ unsigned sCnt;

    unsigned npos = g_npos[b];
    unsigned nneg = g_nneg[b];
    unsigned k = 3u * npos; if (k > nneg) k = nneg;

    unsigned s = 0;
    #pragma unroll 8
    for (int j = 0; j < 64; j++) s += g_hist1[b][t * 64 + j];
    csum[t] = s;
    __syncthreads();
    if (t == 0) {
        unsigned acc = 0;
        for (int i = 1023; i >= 0; i--) { suf[i] = acc; acc += csum[i]; }
        sB1 = 0x7FFFFFFF;   // sentinel (k==0 case): never matched in pass3
        sCnt = 0u;
    }
    __syncthreads();
    if (k > 0) {
        unsigned before = suf[t];
        if (before < k && before + csum[t] >= k) {
            unsigned cum = before;
            for (int j = 63; j >= 0; j--) {
                unsigned c = g_hist1[b][t * 64 + j];
                if (cum + c >= k) { sB1 = t * 64 + j; sCnt = cum; break; }
                cum += c;
            }
        }
    }
    __syncthreads();
    if (t == 0) { g_k[b] = k; g_B1[b] = (unsigned)sB1; g_cntA[b] = sCnt; }
}

__global__ void __launch_bounds__(NT) pass3_kernel() {
    __shared__ float sred[8];
    int b = blockIdx.x / PB;
    int base4 = (blockIdx.x % PB) * CHUNK4;
    unsigned B1 = g_B1[b];
    const uint4* nb4 = reinterpret_cast<const uint4*>(g_negbits) + (size_t)b * HW4;

    float sp2a = 0.f;
    #pragma unroll
    for (int i = 0; i < 4; i++) {
        uint4 v = nb4[base4 + threadIdx.x + i * NT];
        #define PROC3(COMP)                                                       \
        {                                                                         \
            unsigned bits = v.COMP;                                               \
            if (bits) {                                                           \
                unsigned h = bits >> 16;                                          \
                if (h > B1) { float p = __uint_as_float(bits); sp2a += p * p; }   \
                else if (h == B1) atomicAdd(&g_hist2[b][bits & 0xFFFFu], 1u);     \
            }                                                                     \
        }
        PROC3(x) PROC3(y) PROC3(z) PROC3(w)
        #undef PROC3
    }
    float t = blockReduceF(sp2a, sred);
    if (threadIdx.x == 0) atomicAdd(&g_sp2_above[b], (double)t);
}

// resolve low 16 bits of threshold, exact hard-negative p^2 sum, per-batch text dice
__global__ void __launch_bounds__(1024) pass4_kernel() {
    int b = blockIdx.x;
    int t = threadIdx.x;
    __shared__ unsigned csum[1024];
    __shared__ unsigned suf[1024];
    __shared__ int sJ;
    __shared__ unsigned sCnt;
    __shared__ double dred[1024];

    unsigned k = g_k[b];
    unsigned cA = g_cntA[b];
    long long r = (long long)k - (long long)cA;
    unsigned B1 = g_B1[b];
    __shared__ double sHard;
    if (t == 0) sHard = g_sp2_above[b];

    if (r > 0) {
        unsigned s = 0;
        #pragma unroll 8
        for (int j = 0; j < 64; j++) s += g_hist2[b][t * 64 + j];
        csum[t] = s;
        __syncthreads();
        if (t == 0) {
            unsigned acc = 0;
            for (int i = 1023; i >= 0; i--) { suf[i] = acc; acc += csum[i]; }
            sJ = -1; sCnt = 0u;
        }
        __syncthreads();
        unsigned before = suf[t];
        if ((long long)before < r && (long long)(before + csum[t]) >= r) {
            unsigned cum = before;
            for (int j = 63; j >= 0; j--) {
                unsigned c = g_hist2[b][t * 64 + j];
                if ((long long)(cum + c) >= r) { sJ = t * 64 + j; sCnt = cum; break; }
                cum += c;
            }
        }
        __syncthreads();
        int jt = sJ;
        unsigned cAJ = sCnt;
        double ws = 0.0;
        for (int j = 0; j < 64; j++) {
            int gj = t * 64 + j;
            if (gj > jt) {
                unsigned c = g_hist2[b][gj];
                if (c) {
                    float v = __uint_as_float((B1 << 16) | (unsigned)gj);
                    ws += (double)c * (double)v * (double)v;
                }
            }
        }
        dred[t] = ws;
        __syncthreads();
        for (int o = 512; o; o >>= 1) {
            if (t < o) dred[t] += dred[t + o];
            __syncthreads();
        }
        if (t == 0) {
            float vt = __uint_as_float((B1 << 16) | (unsigned)jt);
            sHard += dred[0] + (double)(r - (long long)cAJ) * (double)vt * (double)vt;
        }
        __syncthreads();
    }
    if (t == 0) {
        double np = (double)g_npos[b];
        g_losstext[b] = 1.0 - 2.0 * g_sp[b] / (g_sp2[b] + sHard + np + EPSL);
    }
}

__global__ void final_kernel(float* out) {
    if (threadIdx.x == 0) {
        double lk = 0.0;
        for (int i = 0; i < BATCH * NKC; i++)
            lk += 1.0 - 2.0 * g_ki[i] / (g_kii[i] + g_ktt[i] + EPSL);
        lk /= (double)(BATCH * NKC);
        double lt = 0.0;
        for (int bb = 0; bb < BATCH; bb++) lt += g_losstext[bb];
        lt /= (double)BATCH;
        out[0] = (float)(lk + 0.5 * lt);
        out[1] = (float)lt;
        out[2] = (float)lk;
    }
}

// ---------------- launch ----------------
extern "C" void kernel_launch(void* const* d_in, const int* in_sizes, int n_in,
                              void* d_out, int out_size) {
    const float4* pred = (const float4*)d_in[0];
    const float4* gtt  = (const float4*)d_in[1];
    const float4* gtk  = (const float4*)d_in[2];
    const float4* msk  = (const float4*)d_in[3];
    float* out = (float*)d_out;

    zero_kernel<<<1024, 1024>>>();
    pass1_kernel<<<BATCH * PB, NT>>>(pred, gtt, gtk, msk);
    pass2_kernel<<<BATCH, 1024>>>();
    pass3_kernel<<<BATCH * PB, NT>>>();
    pass4_kernel<<<BATCH, 1024>>>();
    final_kernel<<<1, 32>>>(out);
}